// round 15
// baseline (speedup 1.0000x reference)
#include <cuda_runtime.h>
#include <cuda_bf16.h>
#include <cstdint>

#define N_NODES 30000
#define DEG 8
#define HID 256
#define IN_F 64
#define NE (N_NODES * DEG)

// ---------------- scratch (device globals; no allocations allowed) ----------
__device__ float g_Q[N_NODES * HID];
__device__ float g_K[N_NODES * HID];
__device__ float g_V[N_NODES * HID];
__device__ float g_S[N_NODES * HID];
__device__ float g_H[N_NODES * HID];
__device__ float g_P[N_NODES * DEG];
__device__ float g_part_sum[240 * HID];
__device__ float g_part_sq[240 * HID];
__device__ float g_scale[HID];
__device__ float g_shift[HID];
// split bf16 operands: A2 = [Ah | Al] (M x 2K); B2[slot] = [Bh | Bl] ([256 x 2K])
__device__ __nv_bfloat16 g_Aaug[N_NODES * 2 * HID];
#define B2_BASE (4 * 256 * 2 * IN_F)
__device__ __nv_bfloat16 g_Baug[B2_BASE + 4 * 256 * 2 * HID];

// ---------------- HMMA m16n8k16 bf16 + ldmatrix + cp.async --------------------
__device__ __forceinline__ void mma16816(float* c,
    uint32_t a0, uint32_t a1, uint32_t a2, uint32_t a3,
    uint32_t b0, uint32_t b1)
{
    asm volatile(
        "mma.sync.aligned.m16n8k16.row.col.f32.bf16.bf16.f32 "
        "{%0,%1,%2,%3}, {%4,%5,%6,%7}, {%8,%9}, {%0,%1,%2,%3};"
        : "+f"(c[0]), "+f"(c[1]), "+f"(c[2]), "+f"(c[3])
        : "r"(a0), "r"(a1), "r"(a2), "r"(a3), "r"(b0), "r"(b1));
}

#define LDSM4(r0, r1, r2, r3, addr) \
    asm volatile("ldmatrix.sync.aligned.m8n8.x4.shared.b16 {%0,%1,%2,%3}, [%4];" \
        : "=r"(r0), "=r"(r1), "=r"(r2), "=r"(r3) : "r"(addr))

#define CP16(dst, src, srcsz) \
    asm volatile("cp.async.cg.shared.global [%0], [%1], 16, %2;" \
        :: "r"(dst), "l"(src), "r"(srcsz) : "memory")
#define CPCOMMIT() asm volatile("cp.async.commit_group;" ::: "memory")
#define CPWAIT0() asm volatile("cp.async.wait_group 0;" ::: "memory")
#define CPWAIT1() asm volatile("cp.async.wait_group 1;" ::: "memory")

__device__ __forceinline__ uint32_t smem_u32(const void* p) {
    uint32_t a;
    asm("{ .reg .u64 t; cvta.to.shared.u64 t, %1; cvt.u32.u64 %0, t; }" : "=r"(a) : "l"(p));
    return a;
}

// gemm tile: 128 rows x 32 k-elems bf16, row stride 80B
#define ROWB 80
#define TILE_B (128 * ROWB)
#define BUF_B (4 * TILE_B)
#define SMEM_DYN (2 * BUF_B)

// ---------------- batched GEMM: C[slot][M,256] = fp32(A) @ W^T + bias ---------
__global__ __launch_bounds__(256, 2) void gemm_mma(
    int K, const __nv_bfloat16* __restrict__ Bbase,
    const float* __restrict__ bq, const float* __restrict__ bk,
    const float* __restrict__ bv, const float* __restrict__ bs)
{
    extern __shared__ char sm[];
    const uint32_t smb = smem_u32(sm);

    const int tid = threadIdx.x;
    const int lane = tid & 31, w = tid >> 5;
    const int g = lane >> 2, t4 = lane & 3;
    const int sub = lane >> 3, le = lane & 7;
    const int wm = w & 1, wn = w >> 1;
    const int m0 = blockIdx.x * 128, n0 = blockIdx.y * 128;
    const int slot = blockIdx.z;
    const int K2 = 2 * K;

    const __nv_bfloat16* Bg = Bbase + (size_t)slot * 256 * K2;
    float* C = (slot == 0) ? g_Q : (slot == 1) ? g_K : (slot == 2) ? g_V : g_S;
    const float* bias = (slot == 0) ? bq : (slot == 1) ? bk : (slot == 2) ? bv : bs;

    const uint32_t aconst = (uint32_t)((wm * 64 + (sub & 1) * 8 + le) * ROWB + (sub >> 1) * 16);
    const uint32_t bconst = (uint32_t)((wn * 32 + (sub >> 1) * 8 + le) * ROWB + (sub & 1) * 16);

    float acc[4][4][4];
#pragma unroll
    for (int mi = 0; mi < 4; mi++)
#pragma unroll
        for (int ni = 0; ni < 4; ni++)
#pragma unroll
            for (int q = 0; q < 4; q++) acc[mi][ni][q] = 0.f;

    const int r0 = tid >> 2;
    const int cw0 = (tid & 3) << 3;
    const uint32_t cvb = (uint32_t)((tid & 3) << 4);

#define ISSUE(chunk, buf) do { \
    const int k0 = (chunk) << 5; \
    const uint32_t bb = smb + (buf) * BUF_B; \
    _Pragma("unroll") \
    for (int j = 0; j < 2; j++) { \
        int rr = r0 + j * 64; \
        uint32_t dro = (uint32_t)rr * ROWB + cvb; \
        int gm = m0 + rr; \
        const __nv_bfloat16* sa = g_Aaug + (size_t)gm * K2 + k0 + cw0; \
        int asz = (gm < N_NODES) ? 16 : 0; \
        CP16(bb + dro, sa, asz); \
        CP16(bb + TILE_B + dro, sa + K, asz); \
        const __nv_bfloat16* sb = Bg + (size_t)(n0 + rr) * K2 + k0 + cw0; \
        CP16(bb + 2 * TILE_B + dro, sb, 16); \
        CP16(bb + 3 * TILE_B + dro, sb + K, 16); \
    } } while (0)

    ISSUE(0, 0);
    CPCOMMIT();

    const int nch = K >> 5;
    for (int c = 0; c < nch; c++) {
        if (c + 1 < nch) {
            ISSUE(c + 1, (c + 1) & 1);
            CPCOMMIT();
            CPWAIT1();
        } else {
            CPWAIT0();
        }
        __syncthreads();

        const uint32_t bb = smb + (c & 1) * BUF_B;
        const uint32_t bAh = bb, bAl = bb + TILE_B;
        const uint32_t bBh = bb + 2 * TILE_B, bBl = bb + 3 * TILE_B;
#pragma unroll
        for (int ks = 0; ks < 2; ks++) {
            uint32_t ah[4][4], al[4][4], bh[4][2], bl[4][2];
#pragma unroll
            for (int mi = 0; mi < 4; mi++)
                LDSM4(ah[mi][0], ah[mi][1], ah[mi][2], ah[mi][3],
                      bAh + aconst + mi * (16 * ROWB) + ks * 32);
#pragma unroll
            for (int p = 0; p < 2; p++)
                LDSM4(bh[2 * p][0], bh[2 * p][1], bh[2 * p + 1][0], bh[2 * p + 1][1],
                      bBh + bconst + p * (16 * ROWB) + ks * 32);
#pragma unroll
            for (int p = 0; p < 2; p++)
                LDSM4(bl[2 * p][0], bl[2 * p][1], bl[2 * p + 1][0], bl[2 * p + 1][1],
                      bBl + bconst + p * (16 * ROWB) + ks * 32);
#pragma unroll
            for (int mi = 0; mi < 4; mi++)
#pragma unroll
                for (int ni = 0; ni < 4; ni++)
                    mma16816(acc[mi][ni], ah[mi][0], ah[mi][1], ah[mi][2], ah[mi][3],
                             bh[ni][0], bh[ni][1]);
#pragma unroll
            for (int mi = 0; mi < 4; mi++)
#pragma unroll
                for (int ni = 0; ni < 4; ni++)
                    mma16816(acc[mi][ni], ah[mi][0], ah[mi][1], ah[mi][2], ah[mi][3],
                             bl[ni][0], bl[ni][1]);
#pragma unroll
            for (int mi = 0; mi < 4; mi++)
                LDSM4(al[mi][0], al[mi][1], al[mi][2], al[mi][3],
                      bAl + aconst + mi * (16 * ROWB) + ks * 32);
#pragma unroll
            for (int mi = 0; mi < 4; mi++)
#pragma unroll
                for (int ni = 0; ni < 4; ni++)
                    mma16816(acc[mi][ni], al[mi][0], al[mi][1], al[mi][2], al[mi][3],
                             bh[ni][0], bh[ni][1]);
        }
        __syncthreads();
    }

#pragma unroll
    for (int mi = 0; mi < 4; mi++) {
#pragma unroll
        for (int ni = 0; ni < 4; ni++) {
            int row = m0 + wm * 64 + mi * 16 + g;
            int col = n0 + wn * 32 + ni * 8 + t4 * 2;
            float2 bb2 = *(const float2*)(bias + col);
            if (row < N_NODES) {
                float2 o = make_float2(acc[mi][ni][0] + bb2.x, acc[mi][ni][1] + bb2.y);
                *(float2*)(C + (size_t)row * 256 + col) = o;
            }
            if (row + 8 < N_NODES) {
                float2 o = make_float2(acc[mi][ni][2] + bb2.x, acc[mi][ni][3] + bb2.y);
                *(float2*)(C + (size_t)(row + 8) * 256 + col) = o;
            }
        }
    }
#undef ISSUE
}

// ---------------- operand prep ------------------------------------------------
__global__ __launch_bounds__(256) void prep_A(const float* __restrict__ src,
                                              int M, int Kdim, int bn)
{
    int i = blockIdx.x * blockDim.x + threadIdx.x;
    int vpr = Kdim >> 2;
    if (i >= M * vpr) return;
    int r = i / vpr, c = (i - r * vpr) << 2;
    float4 v = ((const float4*)src)[i];
    if (bn) {
        v.x = fmaxf(v.x * g_scale[c + 0] + g_shift[c + 0], 0.f);
        v.y = fmaxf(v.y * g_scale[c + 1] + g_shift[c + 1], 0.f);
        v.z = fmaxf(v.z * g_scale[c + 2] + g_shift[c + 2], 0.f);
        v.w = fmaxf(v.w * g_scale[c + 3] + g_shift[c + 3], 0.f);
    }
    float hx = __bfloat162float(__float2bfloat16(v.x));
    float hy = __bfloat162float(__float2bfloat16(v.y));
    float hz = __bfloat162float(__float2bfloat16(v.z));
    float hw = __bfloat162float(__float2bfloat16(v.w));
    __nv_bfloat162 h0 = __floats2bfloat162_rn(hx, hy);
    __nv_bfloat162 h1 = __floats2bfloat162_rn(hz, hw);
    __nv_bfloat162 l0 = __floats2bfloat162_rn(v.x - hx, v.y - hy);
    __nv_bfloat162 l1 = __floats2bfloat162_rn(v.z - hz, v.w - hw);
    size_t base = (size_t)r * 2 * Kdim;
    __nv_bfloat162* p0 = (__nv_bfloat162*)(g_Aaug + base + c);
    __nv_bfloat162* p1 = (__nv_bfloat162*)(g_Aaug + base + Kdim + c);
    p0[0] = h0; p0[1] = h1;
    p1[0] = l0; p1[1] = l1;
}

// both layers' weights in ONE launch: slots 0-3 = layer1 (K=64), 4-7 = layer2 (K=256)
__global__ __launch_bounds__(256) void prep_B8(
    const float* __restrict__ W0, const float* __restrict__ W1,
    const float* __restrict__ W2, const float* __restrict__ W3,
    const float* __restrict__ W4, const float* __restrict__ W5,
    const float* __restrict__ W6, const float* __restrict__ W7)
{
    int slot = blockIdx.z;
    int K = (slot < 4) ? IN_F : HID;
    int i = blockIdx.x * blockDim.x + threadIdx.x;
    if (i >= K * 256) return;
    const float* Wt[8] = {W0, W1, W2, W3, W4, W5, W6, W7};
    const float* W = Wt[slot];
    int k = i >> 8, n = i & 255;
    float wv = W[i];
    __nv_bfloat16 h = __float2bfloat16(wv);
    __nv_bfloat16 l = __float2bfloat16(wv - __bfloat162float(h));
    int base = (slot < 4) ? 0 : B2_BASE;
    int s4 = slot & 3;
    __nv_bfloat16* row = g_Baug + base + (size_t)s4 * 256 * 2 * K + (size_t)n * 2 * K;
    row[k] = h;
    row[K + k] = l;
}

// ---------------- window-8 TransformerConv attention (warp per node) ---------
// mode=1: apply ReLU and fuse layer-3 proj8; H store elided (dead — proj
// consumes h2 from registers). h register layout: a0 = h[8*lane..8*lane+3],
// a1 = h[8*lane+4..8*lane+7]; W read with matching indices lane*2(+1).
__global__ __launch_bounds__(256) void attn_kernel(
    int mode,
    const float* __restrict__ Wq3, const float* __restrict__ Wk3,
    const float* __restrict__ Wv3, const float* __restrict__ Ws3)
{
    const int d = blockIdx.x * 8 + (threadIdx.x >> 5);
    const int lane = threadIdx.x & 31;
    if (d >= N_NODES) return;

    const float4* q4 = (const float4*)(g_Q + (size_t)d * HID);
    float4 q0 = q4[lane * 2], q1 = q4[lane * 2 + 1];

    float lg[8];
#pragma unroll
    for (int c = 0; c < 8; c++) {
        int u = d - 1 - c;
        if (u < 0) u += N_NODES;
        const float4* k4 = (const float4*)(g_K + (size_t)u * HID);
        float4 k0 = k4[lane * 2], k1 = k4[lane * 2 + 1];
        float s = q0.x * k0.x + q0.y * k0.y + q0.z * k0.z + q0.w * k0.w
                + q1.x * k1.x + q1.y * k1.y + q1.z * k1.z + q1.w * k1.w;
#pragma unroll
        for (int o = 16; o; o >>= 1) s += __shfl_xor_sync(0xffffffffu, s, o);
        lg[c] = s * 0.0625f;
    }

    float m = lg[0];
#pragma unroll
    for (int c = 1; c < 8; c++) m = fmaxf(m, lg[c]);
    float den = 0.f;
#pragma unroll
    for (int c = 0; c < 8; c++) { lg[c] = expf(lg[c] - m); den += lg[c]; }
    float inv = 1.f / (den + 1e-16f);

    const float4* s4 = (const float4*)(g_S + (size_t)d * HID);
    float4 a0 = s4[lane * 2], a1 = s4[lane * 2 + 1];
#pragma unroll
    for (int c = 0; c < 8; c++) {
        int u = d - 1 - c;
        if (u < 0) u += N_NODES;
        float al = lg[c] * inv;
        const float4* v4 = (const float4*)(g_V + (size_t)u * HID);
        float4 v0 = v4[lane * 2], v1 = v4[lane * 2 + 1];
        a0.x += al * v0.x; a0.y += al * v0.y; a0.z += al * v0.z; a0.w += al * v0.w;
        a1.x += al * v1.x; a1.y += al * v1.y; a1.z += al * v1.z; a1.w += al * v1.w;
    }

    if (mode == 0) {
        float4* h4 = (float4*)(g_H + (size_t)d * HID);
        h4[lane * 2] = a0;
        h4[lane * 2 + 1] = a1;
    } else {
        a0.x = fmaxf(a0.x, 0.f); a0.y = fmaxf(a0.y, 0.f);
        a0.z = fmaxf(a0.z, 0.f); a0.w = fmaxf(a0.w, 0.f);
        a1.x = fmaxf(a1.x, 0.f); a1.y = fmaxf(a1.y, 0.f);
        a1.z = fmaxf(a1.z, 0.f); a1.w = fmaxf(a1.w, 0.f);
        // fused layer-3 proj8 straight from registers (no H store needed)
#pragma unroll
        for (int w8 = 0; w8 < 8; w8++) {
            const float* Wp = (w8 < 2) ? Wq3 : (w8 < 4) ? Wk3 : (w8 < 6) ? Wv3 : Ws3;
            const float4* wr = (const float4*)(Wp + (w8 & 1) * HID);
            float4 w0 = wr[lane * 2], w1 = wr[lane * 2 + 1];
            float s = a0.x * w0.x + a0.y * w0.y + a0.z * w0.z + a0.w * w0.w
                    + a1.x * w1.x + a1.y * w1.y + a1.z * w1.z + a1.w * w1.w;
#pragma unroll
            for (int o = 16; o; o >>= 1) s += __shfl_xor_sync(0xffffffffu, s, o);
            if (lane == 0) g_P[d * 8 + w8] = s;
        }
    }
}

// ---------------- BatchNorm stats (deterministic two-stage) ------------------
__global__ __launch_bounds__(256) void bn_reduce()
{
    const int t = threadIdx.x;
    const int b = blockIdx.x;
    const int r0 = b * 125;
    float s = 0.f, s2 = 0.f;
    for (int r = r0; r < r0 + 125; r++) {
        float v = g_H[(size_t)r * HID + t];
        s += v;
        s2 += v * v;
    }
    g_part_sum[b * HID + t] = s;
    g_part_sq[b * HID + t] = s2;
}

// warp-per-channel finalize: 32 blocks x 8 warps = 256 channels
__global__ __launch_bounds__(256) void bn_finalize(const float* __restrict__ gamma,
                                                   const float* __restrict__ beta)
{
    const int ch = blockIdx.x * 8 + (threadIdx.x >> 5);
    const int lane = threadIdx.x & 31;
    float s = 0.f, s2 = 0.f;
    for (int b = lane; b < 240; b += 32) {
        s += g_part_sum[b * HID + ch];
        s2 += g_part_sq[b * HID + ch];
    }
#pragma unroll
    for (int o = 16; o; o >>= 1) {
        s += __shfl_xor_sync(0xffffffffu, s, o);
        s2 += __shfl_xor_sync(0xffffffffu, s2, o);
    }
    if (lane == 0) {
        float mean = s / (float)N_NODES;
        float var = s2 / (float)N_NODES - mean * mean;
        float sc = gamma[ch] / sqrtf(var + 1e-5f);
        g_scale[ch] = sc;
        g_shift[ch] = beta[ch] - mean * sc;
    }
}

// ---------------- line-graph layer (OUT_F=1, scalar attention) ---------------
__global__ __launch_bounds__(256) void line_out_kernel(
    const float* __restrict__ bq, const float* __restrict__ bk,
    const float* __restrict__ bv, const float* __restrict__ bs,
    float* __restrict__ out)
{
    int t = blockIdx.x * blockDim.x + threadIdx.x;
    if (t >= NE) return;
    const int v = t >> 3, j = t & 7;
    int dstn = v + j + 1;
    if (dstn >= N_NODES) dstn -= N_NODES;

    float q = g_P[v * 8 + 0] + g_P[dstn * 8 + 1] + bq[0];
    float Bk = g_P[v * 8 + 3] + bk[0];
    float Bv = g_P[v * 8 + 5] + bv[0];

    float lg[8];
    float m = -1e30f;
#pragma unroll
    for (int c = 0; c < 8; c++) {
        int u = v - 1 - c;
        if (u < 0) u += N_NODES;
        lg[c] = q * (g_P[u * 8 + 2] + Bk);
        m = fmaxf(m, lg[c]);
    }
    float den = 0.f, agg = 0.f;
#pragma unroll
    for (int c = 0; c < 8; c++) {
        int u = v - 1 - c;
        if (u < 0) u += N_NODES;
        float e = expf(lg[c] - m);
        den += e;
        agg += e * (g_P[u * 8 + 4] + Bv);
    }
    agg /= (den + 1e-16f);
    float s = g_P[v * 8 + 6] + g_P[dstn * 8 + 7] + bs[0];
    float z = agg + s;
    out[t] = 1.f / (1.f + expf(-z));
}

// ---------------- launch ------------------------------------------------------
extern "C" void kernel_launch(void* const* d_in, const int* in_sizes, int n_in,
                              void* d_out, int out_size)
{
    const float* x = (const float*)d_in[0];
    const float* Wq1 = (const float*)d_in[3];
    const float* bq1 = (const float*)d_in[4];
    const float* Wk1 = (const float*)d_in[5];
    const float* bk1 = (const float*)d_in[6];
    const float* Wv1 = (const float*)d_in[7];
    const float* bv1 = (const float*)d_in[8];
    const float* Ws1 = (const float*)d_in[9];
    const float* bs1 = (const float*)d_in[10];
    const float* Wq2 = (const float*)d_in[11];
    const float* bq2 = (const float*)d_in[12];
    const float* Wk2 = (const float*)d_in[13];
    const float* bk2 = (const float*)d_in[14];
    const float* Wv2 = (const float*)d_in[15];
    const float* bv2 = (const float*)d_in[16];
    const float* Ws2 = (const float*)d_in[17];
    const float* bs2 = (const float*)d_in[18];
    const float* Wq3 = (const float*)d_in[19];
    const float* bq3 = (const float*)d_in[20];
    const float* Wk3 = (const float*)d_in[21];
    const float* bk3 = (const float*)d_in[22];
    const float* Wv3 = (const float*)d_in[23];
    const float* bv3 = (const float*)d_in[24];
    const float* Ws3 = (const float*)d_in[25];
    const float* bs3 = (const float*)d_in[26];
    const float* gamma1 = (const float*)d_in[27];
    const float* beta1 = (const float*)d_in[28];

    float* H;
    __nv_bfloat16* Baug;
    cudaGetSymbolAddress((void**)&H, g_H);
    cudaGetSymbolAddress((void**)&Baug, g_Baug);

    cudaFuncSetAttribute(gemm_mma, cudaFuncAttributeMaxDynamicSharedMemorySize, SMEM_DYN);

    dim3 blk(256);
    dim3 ggrid(235, 2, 4);

    // ---- all weight prep in one launch ----
    prep_B8<<<dim3((HID * HID + 255) / 256, 1, 8), blk>>>(
        Wq1, Wk1, Wv1, Ws1, Wq2, Wk2, Wv2, Ws2);

    // ---- layer 1: K=64 ----
    prep_A<<<(N_NODES * IN_F / 4 + 255) / 256, blk>>>(x, N_NODES, IN_F, 0);
    gemm_mma<<<ggrid, blk, SMEM_DYN>>>(IN_F, Baug, bq1, bk1, bv1, bs1);
    attn_kernel<<<(N_NODES + 7) / 8, blk>>>(0, nullptr, nullptr, nullptr, nullptr);

    // ---- BatchNorm stats -> fused scale/shift ----
    bn_reduce<<<240, blk>>>();
    bn_finalize<<<32, blk>>>(gamma1, beta1);

    // ---- layer 2: K=256, BN+ReLU fused into A prep ----
    prep_A<<<(N_NODES * HID / 4 + 255) / 256, blk>>>(H, N_NODES, HID, 1);
    gemm_mma<<<ggrid, blk, SMEM_DYN>>>(HID, Baug + B2_BASE, bq2, bk2, bv2, bs2);
    // attn2: ReLU + fused layer-3 proj8, H store elided (dead)
    attn_kernel<<<(N_NODES + 7) / 8, blk>>>(1, Wq3, Wk3, Wv3, Ws3);

    // ---- layer 3 line attention ----
    line_out_kernel<<<(NE + 255) / 256, blk>>>(bq3, bk3, bv3, bs3, (float*)d_out);
}

// round 16
// speedup vs baseline: 1.4849x; 1.4849x over previous
#include <cuda_runtime.h>
#include <cuda_bf16.h>
#include <cstdint>

#define N_NODES 30000
#define DEG 8
#define HID 256
#define IN_F 64
#define NE (N_NODES * DEG)

// ---------------- scratch (device globals; no allocations allowed) ----------
__device__ float g_Q[N_NODES * HID];
__device__ float g_K[N_NODES * HID];
__device__ float g_V[N_NODES * HID];
__device__ float g_S[N_NODES * HID];
__device__ float g_H[N_NODES * HID];
__device__ float g_P[N_NODES * DEG];
__device__ float g_part_sum[240 * HID];
__device__ float g_part_sq[240 * HID];
__device__ float g_scale[HID];
__device__ float g_shift[HID];
// split bf16 operands: A2 = [Ah | Al] (M x 2K); B2[slot] = [Bh | Bl] ([256 x 2K])
__device__ __nv_bfloat16 g_Aaug[N_NODES * 2 * HID];
#define B2_BASE (4 * 256 * 2 * IN_F)
__device__ __nv_bfloat16 g_Baug[B2_BASE + 4 * 256 * 2 * HID];

// ---------------- HMMA m16n8k16 bf16 + ldmatrix + cp.async --------------------
__device__ __forceinline__ void mma16816(float* c,
    uint32_t a0, uint32_t a1, uint32_t a2, uint32_t a3,
    uint32_t b0, uint32_t b1)
{
    asm volatile(
        "mma.sync.aligned.m16n8k16.row.col.f32.bf16.bf16.f32 "
        "{%0,%1,%2,%3}, {%4,%5,%6,%7}, {%8,%9}, {%0,%1,%2,%3};"
        : "+f"(c[0]), "+f"(c[1]), "+f"(c[2]), "+f"(c[3])
        : "r"(a0), "r"(a1), "r"(a2), "r"(a3), "r"(b0), "r"(b1));
}

#define LDSM4(r0, r1, r2, r3, addr) \
    asm volatile("ldmatrix.sync.aligned.m8n8.x4.shared.b16 {%0,%1,%2,%3}, [%4];" \
        : "=r"(r0), "=r"(r1), "=r"(r2), "=r"(r3) : "r"(addr))

#define CP16(dst, src, srcsz) \
    asm volatile("cp.async.cg.shared.global [%0], [%1], 16, %2;" \
        :: "r"(dst), "l"(src), "r"(srcsz) : "memory")
#define CPCOMMIT() asm volatile("cp.async.commit_group;" ::: "memory")
#define CPWAIT0() asm volatile("cp.async.wait_group 0;" ::: "memory")
#define CPWAIT1() asm volatile("cp.async.wait_group 1;" ::: "memory")

__device__ __forceinline__ uint32_t smem_u32(const void* p) {
    uint32_t a;
    asm("{ .reg .u64 t; cvta.to.shared.u64 t, %1; cvt.u32.u64 %0, t; }" : "=r"(a) : "l"(p));
    return a;
}

// gemm tile: 128 rows x 32 k-elems bf16, row stride 80B
#define ROWB 80
#define TILE_B (128 * ROWB)
#define BUF_B (4 * TILE_B)
#define SMEM_DYN (2 * BUF_B)

// ---------------- batched GEMM: C[slot][M,256] = fp32(A) @ W^T + bias ---------
__global__ __launch_bounds__(256, 2) void gemm_mma(
    int K, const __nv_bfloat16* __restrict__ Bbase,
    const float* __restrict__ bq, const float* __restrict__ bk,
    const float* __restrict__ bv, const float* __restrict__ bs)
{
    extern __shared__ char sm[];
    const uint32_t smb = smem_u32(sm);

    const int tid = threadIdx.x;
    const int lane = tid & 31, w = tid >> 5;
    const int g = lane >> 2, t4 = lane & 3;
    const int sub = lane >> 3, le = lane & 7;
    const int wm = w & 1, wn = w >> 1;
    const int m0 = blockIdx.x * 128, n0 = blockIdx.y * 128;
    const int slot = blockIdx.z;
    const int K2 = 2 * K;

    const __nv_bfloat16* Bg = Bbase + (size_t)slot * 256 * K2;
    float* C = (slot == 0) ? g_Q : (slot == 1) ? g_K : (slot == 2) ? g_V : g_S;
    const float* bias = (slot == 0) ? bq : (slot == 1) ? bk : (slot == 2) ? bv : bs;

    const uint32_t aconst = (uint32_t)((wm * 64 + (sub & 1) * 8 + le) * ROWB + (sub >> 1) * 16);
    const uint32_t bconst = (uint32_t)((wn * 32 + (sub >> 1) * 8 + le) * ROWB + (sub & 1) * 16);

    float acc[4][4][4];
#pragma unroll
    for (int mi = 0; mi < 4; mi++)
#pragma unroll
        for (int ni = 0; ni < 4; ni++)
#pragma unroll
            for (int q = 0; q < 4; q++) acc[mi][ni][q] = 0.f;

    const int r0 = tid >> 2;
    const int cw0 = (tid & 3) << 3;
    const uint32_t cvb = (uint32_t)((tid & 3) << 4);

#define ISSUE(chunk, buf) do { \
    const int k0 = (chunk) << 5; \
    const uint32_t bb = smb + (buf) * BUF_B; \
    _Pragma("unroll") \
    for (int j = 0; j < 2; j++) { \
        int rr = r0 + j * 64; \
        uint32_t dro = (uint32_t)rr * ROWB + cvb; \
        int gm = m0 + rr; \
        const __nv_bfloat16* sa = g_Aaug + (size_t)gm * K2 + k0 + cw0; \
        int asz = (gm < N_NODES) ? 16 : 0; \
        CP16(bb + dro, sa, asz); \
        CP16(bb + TILE_B + dro, sa + K, asz); \
        const __nv_bfloat16* sb = Bg + (size_t)(n0 + rr) * K2 + k0 + cw0; \
        CP16(bb + 2 * TILE_B + dro, sb, 16); \
        CP16(bb + 3 * TILE_B + dro, sb + K, 16); \
    } } while (0)

    ISSUE(0, 0);
    CPCOMMIT();

    const int nch = K >> 5;
    for (int c = 0; c < nch; c++) {
        if (c + 1 < nch) {
            ISSUE(c + 1, (c + 1) & 1);
            CPCOMMIT();
            CPWAIT1();
        } else {
            CPWAIT0();
        }
        __syncthreads();

        const uint32_t bb = smb + (c & 1) * BUF_B;
        const uint32_t bAh = bb, bAl = bb + TILE_B;
        const uint32_t bBh = bb + 2 * TILE_B, bBl = bb + 3 * TILE_B;
#pragma unroll
        for (int ks = 0; ks < 2; ks++) {
            uint32_t ah[4][4], al[4][4], bh[4][2], bl[4][2];
#pragma unroll
            for (int mi = 0; mi < 4; mi++)
                LDSM4(ah[mi][0], ah[mi][1], ah[mi][2], ah[mi][3],
                      bAh + aconst + mi * (16 * ROWB) + ks * 32);
#pragma unroll
            for (int p = 0; p < 2; p++)
                LDSM4(bh[2 * p][0], bh[2 * p][1], bh[2 * p + 1][0], bh[2 * p + 1][1],
                      bBh + bconst + p * (16 * ROWB) + ks * 32);
#pragma unroll
            for (int p = 0; p < 2; p++)
                LDSM4(bl[2 * p][0], bl[2 * p][1], bl[2 * p + 1][0], bl[2 * p + 1][1],
                      bBl + bconst + p * (16 * ROWB) + ks * 32);
#pragma unroll
            for (int mi = 0; mi < 4; mi++)
#pragma unroll
                for (int ni = 0; ni < 4; ni++)
                    mma16816(acc[mi][ni], ah[mi][0], ah[mi][1], ah[mi][2], ah[mi][3],
                             bh[ni][0], bh[ni][1]);
#pragma unroll
            for (int mi = 0; mi < 4; mi++)
#pragma unroll
                for (int ni = 0; ni < 4; ni++)
                    mma16816(acc[mi][ni], ah[mi][0], ah[mi][1], ah[mi][2], ah[mi][3],
                             bl[ni][0], bl[ni][1]);
#pragma unroll
            for (int mi = 0; mi < 4; mi++)
                LDSM4(al[mi][0], al[mi][1], al[mi][2], al[mi][3],
                      bAl + aconst + mi * (16 * ROWB) + ks * 32);
#pragma unroll
            for (int mi = 0; mi < 4; mi++)
#pragma unroll
                for (int ni = 0; ni < 4; ni++)
                    mma16816(acc[mi][ni], al[mi][0], al[mi][1], al[mi][2], al[mi][3],
                             bh[ni][0], bh[ni][1]);
        }
        __syncthreads();
    }

#pragma unroll
    for (int mi = 0; mi < 4; mi++) {
#pragma unroll
        for (int ni = 0; ni < 4; ni++) {
            int row = m0 + wm * 64 + mi * 16 + g;
            int col = n0 + wn * 32 + ni * 8 + t4 * 2;
            float2 bb2 = *(const float2*)(bias + col);
            if (row < N_NODES) {
                float2 o = make_float2(acc[mi][ni][0] + bb2.x, acc[mi][ni][1] + bb2.y);
                *(float2*)(C + (size_t)row * 256 + col) = o;
            }
            if (row + 8 < N_NODES) {
                float2 o = make_float2(acc[mi][ni][2] + bb2.x, acc[mi][ni][3] + bb2.y);
                *(float2*)(C + (size_t)(row + 8) * 256 + col) = o;
            }
        }
    }
#undef ISSUE
}

// ---------------- operand prep ------------------------------------------------
__global__ __launch_bounds__(256) void prep_A(const float* __restrict__ src,
                                              int M, int Kdim, int bn)
{
    int i = blockIdx.x * blockDim.x + threadIdx.x;
    int vpr = Kdim >> 2;
    if (i >= M * vpr) return;
    int r = i / vpr, c = (i - r * vpr) << 2;
    float4 v = ((const float4*)src)[i];
    if (bn) {
        v.x = fmaxf(v.x * g_scale[c + 0] + g_shift[c + 0], 0.f);
        v.y = fmaxf(v.y * g_scale[c + 1] + g_shift[c + 1], 0.f);
        v.z = fmaxf(v.z * g_scale[c + 2] + g_shift[c + 2], 0.f);
        v.w = fmaxf(v.w * g_scale[c + 3] + g_shift[c + 3], 0.f);
    }
    float hx = __bfloat162float(__float2bfloat16(v.x));
    float hy = __bfloat162float(__float2bfloat16(v.y));
    float hz = __bfloat162float(__float2bfloat16(v.z));
    float hw = __bfloat162float(__float2bfloat16(v.w));
    __nv_bfloat162 h0 = __floats2bfloat162_rn(hx, hy);
    __nv_bfloat162 h1 = __floats2bfloat162_rn(hz, hw);
    __nv_bfloat162 l0 = __floats2bfloat162_rn(v.x - hx, v.y - hy);
    __nv_bfloat162 l1 = __floats2bfloat162_rn(v.z - hz, v.w - hw);
    size_t base = (size_t)r * 2 * Kdim;
    __nv_bfloat162* p0 = (__nv_bfloat162*)(g_Aaug + base + c);
    __nv_bfloat162* p1 = (__nv_bfloat162*)(g_Aaug + base + Kdim + c);
    p0[0] = h0; p0[1] = h1;
    p1[0] = l0; p1[1] = l1;
}

__global__ __launch_bounds__(256) void prep_B4(
    const float* __restrict__ W0, const float* __restrict__ W1,
    const float* __restrict__ W2, const float* __restrict__ W3,
    int K, int base)
{
    int i = blockIdx.x * blockDim.x + threadIdx.x;
    if (i >= K * 256) return;
    int slot = blockIdx.z;
    const float* W = (slot == 0) ? W0 : (slot == 1) ? W1 : (slot == 2) ? W2 : W3;
    int k = i >> 8, n = i & 255;
    float wv = W[i];
    __nv_bfloat16 h = __float2bfloat16(wv);
    __nv_bfloat16 l = __float2bfloat16(wv - __bfloat162float(h));
    __nv_bfloat16* row = g_Baug + base + (size_t)slot * 256 * 2 * K + (size_t)n * 2 * K;
    row[k] = h;
    row[K + k] = l;
}

// ---------------- window-8 TransformerConv attention (warp per node) ---------
// relu_proj=1: apply ReLU and fuse layer-3 proj8. Register layout of h2 in
// this kernel: a0 = h[8*lane .. 8*lane+3], a1 = h[8*lane+4 .. 8*lane+7], so W
// must be read with the SAME float4 indices (lane*2, lane*2+1).
__global__ __launch_bounds__(256) void attn_kernel(
    int relu_proj,
    const float* __restrict__ Wq3, const float* __restrict__ Wk3,
    const float* __restrict__ Wv3, const float* __restrict__ Ws3)
{
    const int d = blockIdx.x * 8 + (threadIdx.x >> 5);
    const int lane = threadIdx.x & 31;
    if (d >= N_NODES) return;

    const float4* q4 = (const float4*)(g_Q + (size_t)d * HID);
    float4 q0 = q4[lane * 2], q1 = q4[lane * 2 + 1];

    float lg[8];
#pragma unroll
    for (int c = 0; c < 8; c++) {
        int u = d - 1 - c;
        if (u < 0) u += N_NODES;
        const float4* k4 = (const float4*)(g_K + (size_t)u * HID);
        float4 k0 = k4[lane * 2], k1 = k4[lane * 2 + 1];
        float s = q0.x * k0.x + q0.y * k0.y + q0.z * k0.z + q0.w * k0.w
                + q1.x * k1.x + q1.y * k1.y + q1.z * k1.z + q1.w * k1.w;
#pragma unroll
        for (int o = 16; o; o >>= 1) s += __shfl_xor_sync(0xffffffffu, s, o);
        lg[c] = s * 0.0625f;
    }

    float m = lg[0];
#pragma unroll
    for (int c = 1; c < 8; c++) m = fmaxf(m, lg[c]);
    float den = 0.f;
#pragma unroll
    for (int c = 0; c < 8; c++) { lg[c] = expf(lg[c] - m); den += lg[c]; }
    float inv = 1.f / (den + 1e-16f);

    const float4* s4 = (const float4*)(g_S + (size_t)d * HID);
    float4 a0 = s4[lane * 2], a1 = s4[lane * 2 + 1];
#pragma unroll
    for (int c = 0; c < 8; c++) {
        int u = d - 1 - c;
        if (u < 0) u += N_NODES;
        float al = lg[c] * inv;
        const float4* v4 = (const float4*)(g_V + (size_t)u * HID);
        float4 v0 = v4[lane * 2], v1 = v4[lane * 2 + 1];
        a0.x += al * v0.x; a0.y += al * v0.y; a0.z += al * v0.z; a0.w += al * v0.w;
        a1.x += al * v1.x; a1.y += al * v1.y; a1.z += al * v1.z; a1.w += al * v1.w;
    }
    if (relu_proj) {
        a0.x = fmaxf(a0.x, 0.f); a0.y = fmaxf(a0.y, 0.f);
        a0.z = fmaxf(a0.z, 0.f); a0.w = fmaxf(a0.w, 0.f);
        a1.x = fmaxf(a1.x, 0.f); a1.y = fmaxf(a1.y, 0.f);
        a1.z = fmaxf(a1.z, 0.f); a1.w = fmaxf(a1.w, 0.f);
    }
    float4* h4 = (float4*)(g_H + (size_t)d * HID);
    h4[lane * 2] = a0;
    h4[lane * 2 + 1] = a1;

    if (relu_proj) {
        // fused layer-3 proj8: P[d][w8] = dot(h2[d], W8[w8]); h2 in registers.
        // W read with MATCHING layout: wr[lane*2] pairs with a0, wr[lane*2+1]
        // with a1 (elements 8*lane..8*lane+7).
#pragma unroll
        for (int w8 = 0; w8 < 8; w8++) {
            const float* Wp = (w8 < 2) ? Wq3 : (w8 < 4) ? Wk3 : (w8 < 6) ? Wv3 : Ws3;
            const float4* wr = (const float4*)(Wp + (w8 & 1) * HID);
            float4 w0 = wr[lane * 2], w1 = wr[lane * 2 + 1];
            float s = a0.x * w0.x + a0.y * w0.y + a0.z * w0.z + a0.w * w0.w
                    + a1.x * w1.x + a1.y * w1.y + a1.z * w1.z + a1.w * w1.w;
#pragma unroll
            for (int o = 16; o; o >>= 1) s += __shfl_xor_sync(0xffffffffu, s, o);
            if (lane == 0) g_P[d * 8 + w8] = s;
        }
    }
}

// ---------------- BatchNorm stats (deterministic two-stage) ------------------
__global__ __launch_bounds__(256) void bn_reduce()
{
    const int t = threadIdx.x;
    const int b = blockIdx.x;
    const int r0 = b * 125;
    float s = 0.f, s2 = 0.f;
    for (int r = r0; r < r0 + 125; r++) {
        float v = g_H[(size_t)r * HID + t];
        s += v;
        s2 += v * v;
    }
    g_part_sum[b * HID + t] = s;
    g_part_sq[b * HID + t] = s2;
}

__global__ __launch_bounds__(256) void bn_finalize(const float* __restrict__ gamma,
                                                   const float* __restrict__ beta)
{
    const int t = threadIdx.x;
    float s = 0.f, s2 = 0.f;
    for (int b = 0; b < 240; b++) {
        s += g_part_sum[b * HID + t];
        s2 += g_part_sq[b * HID + t];
    }
    float mean = s / (float)N_NODES;
    float var = s2 / (float)N_NODES - mean * mean;
    float sc = gamma[t] / sqrtf(var + 1e-5f);
    g_scale[t] = sc;
    g_shift[t] = beta[t] - mean * sc;
}

// ---------------- line-graph layer (OUT_F=1, scalar attention) ---------------
__global__ __launch_bounds__(256) void line_out_kernel(
    const float* __restrict__ bq, const float* __restrict__ bk,
    const float* __restrict__ bv, const float* __restrict__ bs,
    float* __restrict__ out)
{
    int t = blockIdx.x * blockDim.x + threadIdx.x;
    if (t >= NE) return;
    const int v = t >> 3, j = t & 7;
    int dstn = v + j + 1;
    if (dstn >= N_NODES) dstn -= N_NODES;

    float q = g_P[v * 8 + 0] + g_P[dstn * 8 + 1] + bq[0];
    float Bk = g_P[v * 8 + 3] + bk[0];
    float Bv = g_P[v * 8 + 5] + bv[0];

    float lg[8];
    float m = -1e30f;
#pragma unroll
    for (int c = 0; c < 8; c++) {
        int u = v - 1 - c;
        if (u < 0) u += N_NODES;
        lg[c] = q * (g_P[u * 8 + 2] + Bk);
        m = fmaxf(m, lg[c]);
    }
    float den = 0.f, agg = 0.f;
#pragma unroll
    for (int c = 0; c < 8; c++) {
        int u = v - 1 - c;
        if (u < 0) u += N_NODES;
        float e = expf(lg[c] - m);
        den += e;
        agg += e * (g_P[u * 8 + 4] + Bv);
    }
    agg /= (den + 1e-16f);
    float s = g_P[v * 8 + 6] + g_P[dstn * 8 + 7] + bs[0];
    float z = agg + s;
    out[t] = 1.f / (1.f + expf(-z));
}

// ---------------- launch ------------------------------------------------------
extern "C" void kernel_launch(void* const* d_in, const int* in_sizes, int n_in,
                              void* d_out, int out_size)
{
    const float* x = (const float*)d_in[0];
    const float* Wq1 = (const float*)d_in[3];
    const float* bq1 = (const float*)d_in[4];
    const float* Wk1 = (const float*)d_in[5];
    const float* bk1 = (const float*)d_in[6];
    const float* Wv1 = (const float*)d_in[7];
    const float* bv1 = (const float*)d_in[8];
    const float* Ws1 = (const float*)d_in[9];
    const float* bs1 = (const float*)d_in[10];
    const float* Wq2 = (const float*)d_in[11];
    const float* bq2 = (const float*)d_in[12];
    const float* Wk2 = (const float*)d_in[13];
    const float* bk2 = (const float*)d_in[14];
    const float* Wv2 = (const float*)d_in[15];
    const float* bv2 = (const float*)d_in[16];
    const float* Ws2 = (const float*)d_in[17];
    const float* bs2 = (const float*)d_in[18];
    const float* Wq3 = (const float*)d_in[19];
    const float* bq3 = (const float*)d_in[20];
    const float* Wk3 = (const float*)d_in[21];
    const float* bk3 = (const float*)d_in[22];
    const float* Wv3 = (const float*)d_in[23];
    const float* bv3 = (const float*)d_in[24];
    const float* Ws3 = (const float*)d_in[25];
    const float* bs3 = (const float*)d_in[26];
    const float* gamma1 = (const float*)d_in[27];
    const float* beta1 = (const float*)d_in[28];

    float* H;
    __nv_bfloat16* Baug;
    cudaGetSymbolAddress((void**)&H, g_H);
    cudaGetSymbolAddress((void**)&Baug, g_Baug);

    cudaFuncSetAttribute(gemm_mma, cudaFuncAttributeMaxDynamicSharedMemorySize, SMEM_DYN);

    dim3 blk(256);
    dim3 ggrid(235, 2, 4);

    // ---- weight prep for both layers up front (2 launches) ----
    prep_B4<<<dim3((IN_F * HID + 255) / 256, 1, 4), blk>>>(Wq1, Wk1, Wv1, Ws1, IN_F, 0);
    prep_B4<<<dim3((HID * HID + 255) / 256, 1, 4), blk>>>(Wq2, Wk2, Wv2, Ws2, HID, B2_BASE);

    // ---- layer 1: K=64 ----
    prep_A<<<(N_NODES * IN_F / 4 + 255) / 256, blk>>>(x, N_NODES, IN_F, 0);
    gemm_mma<<<ggrid, blk, SMEM_DYN>>>(IN_F, Baug, bq1, bk1, bv1, bs1);
    attn_kernel<<<(N_NODES + 7) / 8, blk>>>(0, nullptr, nullptr, nullptr, nullptr);

    // ---- BatchNorm stats -> fused scale/shift ----
    bn_reduce<<<240, blk>>>();
    bn_finalize<<<1, blk>>>(gamma1, beta1);

    // ---- layer 2: K=256, BN+ReLU fused into A prep ----
    prep_A<<<(N_NODES * HID / 4 + 255) / 256, blk>>>(H, N_NODES, HID, 1);
    gemm_mma<<<ggrid, blk, SMEM_DYN>>>(HID, Baug + B2_BASE, bq2, bk2, bv2, bs2);
    // attn2: ReLU + fused layer-3 proj8
    attn_kernel<<<(N_NODES + 7) / 8, blk>>>(1, Wq3, Wk3, Wv3, Ws3);

    // ---- layer 3 line attention ----
    line_out_kernel<<<(NE + 255) / 256, blk>>>(bq3, bk3, bv3, bs3, (float*)d_out);
}

// round 17
// speedup vs baseline: 1.5089x; 1.0162x over previous
#include <cuda_runtime.h>
#include <cuda_bf16.h>
#include <cstdint>

#define N_NODES 30000
#define DEG 8
#define HID 256
#define IN_F 64
#define NE (N_NODES * DEG)

// ---------------- scratch (device globals; no allocations allowed) ----------
__device__ float g_Q[N_NODES * HID];
__device__ float g_K[N_NODES * HID];
__device__ float g_V[N_NODES * HID];
__device__ float g_S[N_NODES * HID];
__device__ float g_H[N_NODES * HID];
__device__ float g_P[N_NODES * DEG];
__device__ float g_part_sum[240 * HID];
__device__ float g_part_sq[240 * HID];
__device__ float g_scale[HID];
__device__ float g_shift[HID];
// split bf16 operands: A2 = [Ah | Al] (M x 2K); B2[slot] = [Bh | Bl] ([256 x 2K])
__device__ __nv_bfloat16 g_Aaug[N_NODES * 2 * HID];
#define B2_BASE (4 * 256 * 2 * IN_F)
__device__ __nv_bfloat16 g_Baug[B2_BASE + 4 * 256 * 2 * HID];

// ---------------- HMMA m16n8k16 bf16 + ldmatrix + cp.async --------------------
__device__ __forceinline__ void mma16816(float* c,
    uint32_t a0, uint32_t a1, uint32_t a2, uint32_t a3,
    uint32_t b0, uint32_t b1)
{
    asm volatile(
        "mma.sync.aligned.m16n8k16.row.col.f32.bf16.bf16.f32 "
        "{%0,%1,%2,%3}, {%4,%5,%6,%7}, {%8,%9}, {%0,%1,%2,%3};"
        : "+f"(c[0]), "+f"(c[1]), "+f"(c[2]), "+f"(c[3])
        : "r"(a0), "r"(a1), "r"(a2), "r"(a3), "r"(b0), "r"(b1));
}

#define LDSM4(r0, r1, r2, r3, addr) \
    asm volatile("ldmatrix.sync.aligned.m8n8.x4.shared.b16 {%0,%1,%2,%3}, [%4];" \
        : "=r"(r0), "=r"(r1), "=r"(r2), "=r"(r3) : "r"(addr))

#define CP16(dst, src, srcsz) \
    asm volatile("cp.async.cg.shared.global [%0], [%1], 16, %2;" \
        :: "r"(dst), "l"(src), "r"(srcsz) : "memory")
#define CPCOMMIT() asm volatile("cp.async.commit_group;" ::: "memory")
#define CPWAIT0() asm volatile("cp.async.wait_group 0;" ::: "memory")
#define CPWAIT1() asm volatile("cp.async.wait_group 1;" ::: "memory")

__device__ __forceinline__ uint32_t smem_u32(const void* p) {
    uint32_t a;
    asm("{ .reg .u64 t; cvta.to.shared.u64 t, %1; cvt.u32.u64 %0, t; }" : "=r"(a) : "l"(p));
    return a;
}

// gemm tile: 128 rows x 32 k-elems bf16, row stride 80B
#define ROWB 80
#define TILE_B (128 * ROWB)
#define BUF_B (4 * TILE_B)
#define SMEM_DYN (2 * BUF_B)

// ---------------- batched GEMM: C[slot][M,256] = fp32(A) @ W^T + bias ---------
__global__ __launch_bounds__(256, 2) void gemm_mma(
    int K, const __nv_bfloat16* __restrict__ Bbase,
    const float* __restrict__ bq, const float* __restrict__ bk,
    const float* __restrict__ bv, const float* __restrict__ bs)
{
    extern __shared__ char sm[];
    const uint32_t smb = smem_u32(sm);

    const int tid = threadIdx.x;
    const int lane = tid & 31, w = tid >> 5;
    const int g = lane >> 2, t4 = lane & 3;
    const int sub = lane >> 3, le = lane & 7;
    const int wm = w & 1, wn = w >> 1;
    const int m0 = blockIdx.x * 128, n0 = blockIdx.y * 128;
    const int slot = blockIdx.z;
    const int K2 = 2 * K;

    const __nv_bfloat16* Bg = Bbase + (size_t)slot * 256 * K2;
    float* C = (slot == 0) ? g_Q : (slot == 1) ? g_K : (slot == 2) ? g_V : g_S;
    const float* bias = (slot == 0) ? bq : (slot == 1) ? bk : (slot == 2) ? bv : bs;

    const uint32_t aconst = (uint32_t)((wm * 64 + (sub & 1) * 8 + le) * ROWB + (sub >> 1) * 16);
    const uint32_t bconst = (uint32_t)((wn * 32 + (sub >> 1) * 8 + le) * ROWB + (sub & 1) * 16);

    float acc[4][4][4];
#pragma unroll
    for (int mi = 0; mi < 4; mi++)
#pragma unroll
        for (int ni = 0; ni < 4; ni++)
#pragma unroll
            for (int q = 0; q < 4; q++) acc[mi][ni][q] = 0.f;

    const int r0 = tid >> 2;
    const int cw0 = (tid & 3) << 3;
    const uint32_t cvb = (uint32_t)((tid & 3) << 4);

#define ISSUE(chunk, buf) do { \
    const int k0 = (chunk) << 5; \
    const uint32_t bb = smb + (buf) * BUF_B; \
    _Pragma("unroll") \
    for (int j = 0; j < 2; j++) { \
        int rr = r0 + j * 64; \
        uint32_t dro = (uint32_t)rr * ROWB + cvb; \
        int gm = m0 + rr; \
        const __nv_bfloat16* sa = g_Aaug + (size_t)gm * K2 + k0 + cw0; \
        int asz = (gm < N_NODES) ? 16 : 0; \
        CP16(bb + dro, sa, asz); \
        CP16(bb + TILE_B + dro, sa + K, asz); \
        const __nv_bfloat16* sb = Bg + (size_t)(n0 + rr) * K2 + k0 + cw0; \
        CP16(bb + 2 * TILE_B + dro, sb, 16); \
        CP16(bb + 3 * TILE_B + dro, sb + K, 16); \
    } } while (0)

    ISSUE(0, 0);
    CPCOMMIT();

    const int nch = K >> 5;
    for (int c = 0; c < nch; c++) {
        if (c + 1 < nch) {
            ISSUE(c + 1, (c + 1) & 1);
            CPCOMMIT();
            CPWAIT1();
        } else {
            CPWAIT0();
        }
        __syncthreads();

        const uint32_t bb = smb + (c & 1) * BUF_B;
        const uint32_t bAh = bb, bAl = bb + TILE_B;
        const uint32_t bBh = bb + 2 * TILE_B, bBl = bb + 3 * TILE_B;
#pragma unroll
        for (int ks = 0; ks < 2; ks++) {
            uint32_t ah[4][4], al[4][4], bh[4][2], bl[4][2];
#pragma unroll
            for (int mi = 0; mi < 4; mi++)
                LDSM4(ah[mi][0], ah[mi][1], ah[mi][2], ah[mi][3],
                      bAh + aconst + mi * (16 * ROWB) + ks * 32);
#pragma unroll
            for (int p = 0; p < 2; p++)
                LDSM4(bh[2 * p][0], bh[2 * p][1], bh[2 * p + 1][0], bh[2 * p + 1][1],
                      bBh + bconst + p * (16 * ROWB) + ks * 32);
#pragma unroll
            for (int p = 0; p < 2; p++)
                LDSM4(bl[2 * p][0], bl[2 * p][1], bl[2 * p + 1][0], bl[2 * p + 1][1],
                      bBl + bconst + p * (16 * ROWB) + ks * 32);
#pragma unroll
            for (int mi = 0; mi < 4; mi++)
#pragma unroll
                for (int ni = 0; ni < 4; ni++)
                    mma16816(acc[mi][ni], ah[mi][0], ah[mi][1], ah[mi][2], ah[mi][3],
                             bh[ni][0], bh[ni][1]);
#pragma unroll
            for (int mi = 0; mi < 4; mi++)
#pragma unroll
                for (int ni = 0; ni < 4; ni++)
                    mma16816(acc[mi][ni], ah[mi][0], ah[mi][1], ah[mi][2], ah[mi][3],
                             bl[ni][0], bl[ni][1]);
#pragma unroll
            for (int mi = 0; mi < 4; mi++)
                LDSM4(al[mi][0], al[mi][1], al[mi][2], al[mi][3],
                      bAl + aconst + mi * (16 * ROWB) + ks * 32);
#pragma unroll
            for (int mi = 0; mi < 4; mi++)
#pragma unroll
                for (int ni = 0; ni < 4; ni++)
                    mma16816(acc[mi][ni], al[mi][0], al[mi][1], al[mi][2], al[mi][3],
                             bh[ni][0], bh[ni][1]);
        }
        __syncthreads();
    }

#pragma unroll
    for (int mi = 0; mi < 4; mi++) {
#pragma unroll
        for (int ni = 0; ni < 4; ni++) {
            int row = m0 + wm * 64 + mi * 16 + g;
            int col = n0 + wn * 32 + ni * 8 + t4 * 2;
            float2 bb2 = *(const float2*)(bias + col);
            if (row < N_NODES) {
                float2 o = make_float2(acc[mi][ni][0] + bb2.x, acc[mi][ni][1] + bb2.y);
                *(float2*)(C + (size_t)row * 256 + col) = o;
            }
            if (row + 8 < N_NODES) {
                float2 o = make_float2(acc[mi][ni][2] + bb2.x, acc[mi][ni][3] + bb2.y);
                *(float2*)(C + (size_t)(row + 8) * 256 + col) = o;
            }
        }
    }
#undef ISSUE
}

// ---------------- operand prep ------------------------------------------------
__global__ __launch_bounds__(256) void prep_A(const float* __restrict__ src,
                                              int M, int Kdim, int bn)
{
    int i = blockIdx.x * blockDim.x + threadIdx.x;
    int vpr = Kdim >> 2;
    if (i >= M * vpr) return;
    int r = i / vpr, c = (i - r * vpr) << 2;
    float4 v = ((const float4*)src)[i];
    if (bn) {
        v.x = fmaxf(v.x * g_scale[c + 0] + g_shift[c + 0], 0.f);
        v.y = fmaxf(v.y * g_scale[c + 1] + g_shift[c + 1], 0.f);
        v.z = fmaxf(v.z * g_scale[c + 2] + g_shift[c + 2], 0.f);
        v.w = fmaxf(v.w * g_scale[c + 3] + g_shift[c + 3], 0.f);
    }
    float hx = __bfloat162float(__float2bfloat16(v.x));
    float hy = __bfloat162float(__float2bfloat16(v.y));
    float hz = __bfloat162float(__float2bfloat16(v.z));
    float hw = __bfloat162float(__float2bfloat16(v.w));
    __nv_bfloat162 h0 = __floats2bfloat162_rn(hx, hy);
    __nv_bfloat162 h1 = __floats2bfloat162_rn(hz, hw);
    __nv_bfloat162 l0 = __floats2bfloat162_rn(v.x - hx, v.y - hy);
    __nv_bfloat162 l1 = __floats2bfloat162_rn(v.z - hz, v.w - hw);
    size_t base = (size_t)r * 2 * Kdim;
    __nv_bfloat162* p0 = (__nv_bfloat162*)(g_Aaug + base + c);
    __nv_bfloat162* p1 = (__nv_bfloat162*)(g_Aaug + base + Kdim + c);
    p0[0] = h0; p0[1] = h1;
    p1[0] = l0; p1[1] = l1;
}

__global__ __launch_bounds__(256) void prep_B4(
    const float* __restrict__ W0, const float* __restrict__ W1,
    const float* __restrict__ W2, const float* __restrict__ W3,
    int K, int base)
{
    int i = blockIdx.x * blockDim.x + threadIdx.x;
    if (i >= K * 256) return;
    int slot = blockIdx.z;
    const float* W = (slot == 0) ? W0 : (slot == 1) ? W1 : (slot == 2) ? W2 : W3;
    int k = i >> 8, n = i & 255;
    float wv = W[i];
    __nv_bfloat16 h = __float2bfloat16(wv);
    __nv_bfloat16 l = __float2bfloat16(wv - __bfloat162float(h));
    __nv_bfloat16* row = g_Baug + base + (size_t)slot * 256 * 2 * K + (size_t)n * 2 * K;
    row[k] = h;
    row[K + k] = l;
}

// ---------------- window-8 TransformerConv attention (warp per node) ---------
// relu_proj=1: apply ReLU and fuse layer-3 proj8. Register layout of h2 in
// this kernel: a0 = h[8*lane .. 8*lane+3], a1 = h[8*lane+4 .. 8*lane+7], so W
// must be read with the SAME float4 indices (lane*2, lane*2+1).
__global__ __launch_bounds__(256) void attn_kernel(
    int relu_proj,
    const float* __restrict__ Wq3, const float* __restrict__ Wk3,
    const float* __restrict__ Wv3, const float* __restrict__ Ws3)
{
    const int d = blockIdx.x * 8 + (threadIdx.x >> 5);
    const int lane = threadIdx.x & 31;
    if (d >= N_NODES) return;

    const float4* q4 = (const float4*)(g_Q + (size_t)d * HID);
    float4 q0 = q4[lane * 2], q1 = q4[lane * 2 + 1];

    float lg[8];
#pragma unroll
    for (int c = 0; c < 8; c++) {
        int u = d - 1 - c;
        if (u < 0) u += N_NODES;
        const float4* k4 = (const float4*)(g_K + (size_t)u * HID);
        float4 k0 = k4[lane * 2], k1 = k4[lane * 2 + 1];
        float s = q0.x * k0.x + q0.y * k0.y + q0.z * k0.z + q0.w * k0.w
                + q1.x * k1.x + q1.y * k1.y + q1.z * k1.z + q1.w * k1.w;
#pragma unroll
        for (int o = 16; o; o >>= 1) s += __shfl_xor_sync(0xffffffffu, s, o);
        lg[c] = s * 0.0625f;
    }

    float m = lg[0];
#pragma unroll
    for (int c = 1; c < 8; c++) m = fmaxf(m, lg[c]);
    float den = 0.f;
#pragma unroll
    for (int c = 0; c < 8; c++) { lg[c] = expf(lg[c] - m); den += lg[c]; }
    float inv = 1.f / (den + 1e-16f);

    const float4* s4 = (const float4*)(g_S + (size_t)d * HID);
    float4 a0 = s4[lane * 2], a1 = s4[lane * 2 + 1];
#pragma unroll
    for (int c = 0; c < 8; c++) {
        int u = d - 1 - c;
        if (u < 0) u += N_NODES;
        float al = lg[c] * inv;
        const float4* v4 = (const float4*)(g_V + (size_t)u * HID);
        float4 v0 = v4[lane * 2], v1 = v4[lane * 2 + 1];
        a0.x += al * v0.x; a0.y += al * v0.y; a0.z += al * v0.z; a0.w += al * v0.w;
        a1.x += al * v1.x; a1.y += al * v1.y; a1.z += al * v1.z; a1.w += al * v1.w;
    }
    if (relu_proj) {
        a0.x = fmaxf(a0.x, 0.f); a0.y = fmaxf(a0.y, 0.f);
        a0.z = fmaxf(a0.z, 0.f); a0.w = fmaxf(a0.w, 0.f);
        a1.x = fmaxf(a1.x, 0.f); a1.y = fmaxf(a1.y, 0.f);
        a1.z = fmaxf(a1.z, 0.f); a1.w = fmaxf(a1.w, 0.f);
    }
    float4* h4 = (float4*)(g_H + (size_t)d * HID);
    h4[lane * 2] = a0;
    h4[lane * 2 + 1] = a1;

    if (relu_proj) {
        // fused layer-3 proj8: P[d][w8] = dot(h2[d], W8[w8]); h2 in registers.
        // W read with MATCHING layout: wr[lane*2] pairs with a0, wr[lane*2+1]
        // with a1 (elements 8*lane..8*lane+7).
#pragma unroll
        for (int w8 = 0; w8 < 8; w8++) {
            const float* Wp = (w8 < 2) ? Wq3 : (w8 < 4) ? Wk3 : (w8 < 6) ? Wv3 : Ws3;
            const float4* wr = (const float4*)(Wp + (w8 & 1) * HID);
            float4 w0 = wr[lane * 2], w1 = wr[lane * 2 + 1];
            float s = a0.x * w0.x + a0.y * w0.y + a0.z * w0.z + a0.w * w0.w
                    + a1.x * w1.x + a1.y * w1.y + a1.z * w1.z + a1.w * w1.w;
#pragma unroll
            for (int o = 16; o; o >>= 1) s += __shfl_xor_sync(0xffffffffu, s, o);
            if (lane == 0) g_P[d * 8 + w8] = s;
        }
    }
}

// ---------------- BatchNorm stats (deterministic two-stage) ------------------
__global__ __launch_bounds__(256) void bn_reduce()
{
    const int t = threadIdx.x;
    const int b = blockIdx.x;
    const int r0 = b * 125;
    float s = 0.f, s2 = 0.f;
    for (int r = r0; r < r0 + 125; r++) {
        float v = g_H[(size_t)r * HID + t];
        s += v;
        s2 += v * v;
    }
    g_part_sum[b * HID + t] = s;
    g_part_sq[b * HID + t] = s2;
}

// warp-per-channel finalize: 32 blocks x 8 warps = 256 channels (the sole
// change this round vs the reproduced 330us baseline; replaces the serial
// 1-CTA version whose 240-deep strided loops were latency-exposed).
__global__ __launch_bounds__(256) void bn_finalize(const float* __restrict__ gamma,
                                                   const float* __restrict__ beta)
{
    const int ch = blockIdx.x * 8 + (threadIdx.x >> 5);
    const int lane = threadIdx.x & 31;
    float s = 0.f, s2 = 0.f;
    for (int b = lane; b < 240; b += 32) {
        s += g_part_sum[b * HID + ch];
        s2 += g_part_sq[b * HID + ch];
    }
#pragma unroll
    for (int o = 16; o; o >>= 1) {
        s += __shfl_xor_sync(0xffffffffu, s, o);
        s2 += __shfl_xor_sync(0xffffffffu, s2, o);
    }
    if (lane == 0) {
        float mean = s / (float)N_NODES;
        float var = s2 / (float)N_NODES - mean * mean;
        float sc = gamma[ch] / sqrtf(var + 1e-5f);
        g_scale[ch] = sc;
        g_shift[ch] = beta[ch] - mean * sc;
    }
}

// ---------------- line-graph layer (OUT_F=1, scalar attention) ---------------
__global__ __launch_bounds__(256) void line_out_kernel(
    const float* __restrict__ bq, const float* __restrict__ bk,
    const float* __restrict__ bv, const float* __restrict__ bs,
    float* __restrict__ out)
{
    int t = blockIdx.x * blockDim.x + threadIdx.x;
    if (t >= NE) return;
    const int v = t >> 3, j = t & 7;
    int dstn = v + j + 1;
    if (dstn >= N_NODES) dstn -= N_NODES;

    float q = g_P[v * 8 + 0] + g_P[dstn * 8 + 1] + bq[0];
    float Bk = g_P[v * 8 + 3] + bk[0];
    float Bv = g_P[v * 8 + 5] + bv[0];

    float lg[8];
    float m = -1e30f;
#pragma unroll
    for (int c = 0; c < 8; c++) {
        int u = v - 1 - c;
        if (u < 0) u += N_NODES;
        lg[c] = q * (g_P[u * 8 + 2] + Bk);
        m = fmaxf(m, lg[c]);
    }
    float den = 0.f, agg = 0.f;
#pragma unroll
    for (int c = 0; c < 8; c++) {
        int u = v - 1 - c;
        if (u < 0) u += N_NODES;
        float e = expf(lg[c] - m);
        den += e;
        agg += e * (g_P[u * 8 + 4] + Bv);
    }
    agg /= (den + 1e-16f);
    float s = g_P[v * 8 + 6] + g_P[dstn * 8 + 7] + bs[0];
    float z = agg + s;
    out[t] = 1.f / (1.f + expf(-z));
}

// ---------------- launch ------------------------------------------------------
extern "C" void kernel_launch(void* const* d_in, const int* in_sizes, int n_in,
                              void* d_out, int out_size)
{
    const float* x = (const float*)d_in[0];
    const float* Wq1 = (const float*)d_in[3];
    const float* bq1 = (const float*)d_in[4];
    const float* Wk1 = (const float*)d_in[5];
    const float* bk1 = (const float*)d_in[6];
    const float* Wv1 = (const float*)d_in[7];
    const float* bv1 = (const float*)d_in[8];
    const float* Ws1 = (const float*)d_in[9];
    const float* bs1 = (const float*)d_in[10];
    const float* Wq2 = (const float*)d_in[11];
    const float* bq2 = (const float*)d_in[12];
    const float* Wk2 = (const float*)d_in[13];
    const float* bk2 = (const float*)d_in[14];
    const float* Wv2 = (const float*)d_in[15];
    const float* bv2 = (const float*)d_in[16];
    const float* Ws2 = (const float*)d_in[17];
    const float* bs2 = (const float*)d_in[18];
    const float* Wq3 = (const float*)d_in[19];
    const float* bq3 = (const float*)d_in[20];
    const float* Wk3 = (const float*)d_in[21];
    const float* bk3 = (const float*)d_in[22];
    const float* Wv3 = (const float*)d_in[23];
    const float* bv3 = (const float*)d_in[24];
    const float* Ws3 = (const float*)d_in[25];
    const float* bs3 = (const float*)d_in[26];
    const float* gamma1 = (const float*)d_in[27];
    const float* beta1 = (const float*)d_in[28];

    float* H;
    __nv_bfloat16* Baug;
    cudaGetSymbolAddress((void**)&H, g_H);
    cudaGetSymbolAddress((void**)&Baug, g_Baug);

    cudaFuncSetAttribute(gemm_mma, cudaFuncAttributeMaxDynamicSharedMemorySize, SMEM_DYN);

    dim3 blk(256);
    dim3 ggrid(235, 2, 4);

    // ---- weight prep for both layers up front (2 launches) ----
    prep_B4<<<dim3((IN_F * HID + 255) / 256, 1, 4), blk>>>(Wq1, Wk1, Wv1, Ws1, IN_F, 0);
    prep_B4<<<dim3((HID * HID + 255) / 256, 1, 4), blk>>>(Wq2, Wk2, Wv2, Ws2, HID, B2_BASE);

    // ---- layer 1: K=64 ----
    prep_A<<<(N_NODES * IN_F / 4 + 255) / 256, blk>>>(x, N_NODES, IN_F, 0);
    gemm_mma<<<ggrid, blk, SMEM_DYN>>>(IN_F, Baug, bq1, bk1, bv1, bs1);
    attn_kernel<<<(N_NODES + 7) / 8, blk>>>(0, nullptr, nullptr, nullptr, nullptr);

    // ---- BatchNorm stats -> fused scale/shift ----
    bn_reduce<<<240, blk>>>();
    bn_finalize<<<32, blk>>>(gamma1, beta1);

    // ---- layer 2: K=256, BN+ReLU fused into A prep ----
    prep_A<<<(N_NODES * HID / 4 + 255) / 256, blk>>>(H, N_NODES, HID, 1);
    gemm_mma<<<ggrid, blk, SMEM_DYN>>>(HID, Baug + B2_BASE, bq2, bk2, bv2, bs2);
    // attn2: ReLU + fused layer-3 proj8
    attn_kernel<<<(N_NODES + 7) / 8, blk>>>(1, Wq3, Wk3, Wv3, Ws3);

    // ---- layer 3 line attention ----
    line_out_kernel<<<(NE + 255) / 256, blk>>>(bq3, bk3, bv3, bs3, (float*)d_out);
}